// round 12
// baseline (speedup 1.0000x reference)
#include <cuda_runtime.h>
#include <cuda_bf16.h>
#include <cstdint>

#define NN 100000
#define NE 800000
#define H  64
#define NT 256
#define NBLK 391
#define PPIT 144   // proj smem row pitch bytes (72 bf16)
#define UPIT 272   // upd smem row pitch bytes (136 bf16)

#define SMEM_PROJT (6 * 128 * PPIT)                         // A0(H,L) A1(H,L) BH BL
#define SMEM_UPDT  (2 * 128 * UPIT + 2 * 64 * UPIT + 768)   // AH AL BH BL + params

// Scratch (device globals: allocation-free rule)
__device__ __align__(16) float g_x[(size_t)NN * H];
__device__ __align__(16) float g_p1[(size_t)NN * H];
__device__ __align__(16) float g_p2[(size_t)NN * H];
__device__ __align__(16) __nv_bfloat162 g_xh[(size_t)NN * 32];
__device__ __align__(16) __nv_bfloat162 g_xl[(size_t)NN * 32];
__device__ __align__(16) __nv_bfloat162 g_ah[(size_t)NN * 32];
__device__ __align__(16) __nv_bfloat162 g_al[(size_t)NN * 32];
__device__ __align__(16) __nv_bfloat16 g_bh[3 * 128 * 72];   // proj W hi [C][k] pitch 72
__device__ __align__(16) __nv_bfloat16 g_bl[3 * 128 * 72];
__device__ __align__(16) __nv_bfloat16 g_uh[3 * 64 * 136];   // upd W hi [C][k] pitch 136
__device__ __align__(16) __nv_bfloat16 g_ul[3 * 64 * 136];
__device__ int g_deg[NN];
__device__ int g_off[NN + 1];
__device__ int g_cur[NN];
__device__ int g_csr[NE];
__device__ int g_bsum[NBLK];
__device__ int g_boff[NBLK];
__device__ float g_sum[H];
__device__ unsigned g_maxb[H];

// ---------- helpers ----------
__device__ __forceinline__ unsigned encf(float f) {
    unsigned u = __float_as_uint(f);
    return (u & 0x80000000u) ? ~u : (u | 0x80000000u);
}
__device__ __forceinline__ float decf(unsigned u) {
    return (u & 0x80000000u) ? __uint_as_float(u & 0x7FFFFFFFu) : __uint_as_float(~u);
}
__device__ __forceinline__ void split2(float a, float b, __nv_bfloat162& h, __nv_bfloat162& lo) {
    __nv_bfloat16 ha = __float2bfloat16(a), hb = __float2bfloat16(b);
    h = __halves2bfloat162(ha, hb);
    lo = __halves2bfloat162(__float2bfloat16(a - __bfloat162float(ha)),
                            __float2bfloat16(b - __bfloat162float(hb)));
}
__device__ __forceinline__ void ldsm4(unsigned& r0, unsigned& r1, unsigned& r2, unsigned& r3,
                                      uint32_t addr) {
    asm volatile("ldmatrix.sync.aligned.m8n8.x4.shared.b16 {%0,%1,%2,%3}, [%4];"
                 : "=r"(r0), "=r"(r1), "=r"(r2), "=r"(r3) : "r"(addr));
}
__device__ __forceinline__ void mma16816(float* c, const unsigned* a, const unsigned* b) {
    asm volatile("mma.sync.aligned.m16n8k16.row.col.f32.bf16.bf16.f32 "
                 "{%0,%1,%2,%3}, {%4,%5,%6,%7}, {%8,%9}, {%0,%1,%2,%3};"
                 : "+f"(c[0]), "+f"(c[1]), "+f"(c[2]), "+f"(c[3])
                 : "r"(a[0]), "r"(a[1]), "r"(a[2]), "r"(a[3]), "r"(b[0]), "r"(b[1]));
}
__device__ __forceinline__ void cpa16(void* dst, const void* src) {
    unsigned d = (unsigned)__cvta_generic_to_shared(dst);
    asm volatile("cp.async.ca.shared.global [%0], [%1], 16;" :: "r"(d), "l"(src));
}
#define CPA_COMMIT() asm volatile("cp.async.commit_group;")
#define CPA_WAIT0()  asm volatile("cp.async.wait_group 0;")
#define CPA_WAIT1()  asm volatile("cp.async.wait_group 1;")

// ---------- merged setup: embed + weight prepack ----------
__global__ void k_setup(const int* __restrict__ ti, const float* __restrict__ et,
                        const int* __restrict__ edges,
                        const float* __restrict__ msg_w, const float* __restrict__ upd_w) {
    int i = blockIdx.x * blockDim.x + threadIdx.x;
    int stride = gridDim.x * blockDim.x;
    for (int lin = i; lin < NN * 16; lin += stride) {
        int n = lin >> 4, q = lin & 15;
        float4 v = ((const float4*)et)[ti[n] * 16 + q];
        ((float4*)g_x)[lin] = v;
        __nv_bfloat162 h0, l0, h1, l1;
        split2(v.x, v.y, h0, l0);
        split2(v.z, v.w, h1, l1);
        g_xh[lin * 2] = h0; g_xh[lin * 2 + 1] = h1;
        g_xl[lin * 2] = l0; g_xl[lin * 2 + 1] = l1;
    }
    for (int n = i; n < NN; n += stride) g_deg[n] = 0;
    if (i < H) { g_sum[i] = 0.f; g_maxb[i] = 0u; }
    for (int idx = i; idx < 3 * 128 * 72; idx += stride) {
        int l = idx / (128 * 72), r = idx % (128 * 72);
        int C = r / 72, k = r % 72;
        __nv_bfloat16 h = __float2bfloat16(0.f), lo = h;
        if (k < 64) {
            float v = msg_w[l * 8192 + (k + (C & 64)) * 64 + (C & 63)];
            h = __float2bfloat16(v);
            lo = __float2bfloat16(v - __bfloat162float(h));
        }
        g_bh[idx] = h; g_bl[idx] = lo;
    }
    for (int idx = i; idx < 3 * 64 * 136; idx += stride) {
        int l = idx / (64 * 136), r = idx % (64 * 136);
        int C = r / 136, k = r % 136;
        __nv_bfloat16 h = __float2bfloat16(0.f), lo = h;
        if (k < 128) {
            float v = upd_w[l * 8192 + k * 64 + C];
            h = __float2bfloat16(v);
            lo = __float2bfloat16(v - __bfloat162float(h));
        }
        g_uh[idx] = h; g_ul[idx] = lo;
    }
}

__global__ void k_hist(const int* __restrict__ edges) {
    int i = blockIdx.x * blockDim.x + threadIdx.x;
    int stride = gridDim.x * blockDim.x;
    for (int e = i; e < NE; e += stride)
        atomicAdd(&g_deg[((const int2*)edges)[e].y], 1);
}

// ---------- exclusive scan ----------
__global__ void k_scan1() {
    __shared__ int s[256];
    int t = threadIdx.x;
    int i = blockIdx.x * 256 + t;
    int v = (i < NN) ? g_deg[i] : 0;
    s[t] = v;
    __syncthreads();
    #pragma unroll
    for (int d = 1; d < 256; d <<= 1) {
        int tv = (t >= d) ? s[t - d] : 0;
        __syncthreads();
        s[t] += tv;
        __syncthreads();
    }
    if (i < NN) g_off[i] = s[t] - v;
    if (t == 255) g_bsum[blockIdx.x] = s[255];
}

__global__ void k_scan2() {
    __shared__ int s[512];
    int t = threadIdx.x;
    int v = (t < NBLK) ? g_bsum[t] : 0;
    s[t] = v;
    __syncthreads();
    #pragma unroll
    for (int d = 1; d < 512; d <<= 1) {
        int tv = (t >= d) ? s[t - d] : 0;
        __syncthreads();
        s[t] += tv;
        __syncthreads();
    }
    if (t < NBLK) g_boff[t] = s[t] - v;
}

__global__ void k_scan3() {
    int i = blockIdx.x * blockDim.x + threadIdx.x;
    if (i < NN) {
        int val = g_off[i] + g_boff[i >> 8];
        g_off[i] = val;
        g_cur[i] = val;
    }
    if (i == 0) g_off[NN] = NE;
}

__global__ void k_scatter(const int* __restrict__ edges) {
    int e = blockIdx.x * blockDim.x + threadIdx.x;
    if (e < NE) {
        int2 ed = ((const int2*)edges)[e];
        int pos = atomicAdd(&g_cur[ed.y], 1);
        g_csr[pos] = ed.x;
    }
}

// ---------- tensor-core projection (double-buffered A) ----------
__global__ __launch_bounds__(256, 2) void k_proj_t(int layer, const float* __restrict__ msg_b) {
    extern __shared__ char smc[];
    char* Abuf[2] = { smc, smc + 2 * 128 * PPIT };   // each: AH then AL
    char* BH = smc + 4 * 128 * PPIT;
    char* BL = BH + 128 * PPIT;

    const int tid = threadIdx.x;
    const int w = tid >> 5, l = tid & 31;

    {
        const uint4* sh = (const uint4*)(g_bh + layer * 128 * 72);
        const uint4* sl = (const uint4*)(g_bl + layer * 128 * 72);
        for (int i = tid; i < 1152; i += 256) {
            ((uint4*)BH)[i] = sh[i];
            ((uint4*)BL)[i] = sl[i];
        }
    }
    float2 bias2[8];
    #pragma unroll
    for (int i = 0; i < 8; i++) bias2[i] = *(const float2*)(msg_b + i * 8 + (l & 3) * 2);

    const uint32_t a_loff = (uint32_t)(((w << 4) + (l & 15)) * PPIT) + ((l >> 4) ? 16u : 0u);
    const uint32_t b_loff = (uint32_t)((l & 7) * PPIT) + (((l >> 3) & 1) ? 16u : 0u)
                          + (((l >> 4) & 1) ? 8u * PPIT : 0u);
    const uint32_t bH = (uint32_t)__cvta_generic_to_shared(BH) + b_loff;
    const uint32_t bL = (uint32_t)__cvta_generic_to_shared(BL) + b_loff;

    const uint4* xh4 = (const uint4*)g_xh;
    const uint4* xl4 = (const uint4*)g_xl;

    const int ntiles = (NN + 127) / 128;

    auto stageA = [&](char* buf, int base) {
        char* ah = buf;
        char* al = buf + 128 * PPIT;
        #pragma unroll
        for (int s = 0; s < 4; s++) {
            int i = s * 256 + tid;
            int r = i >> 3, q = i & 7;
            int gn = base + r; if (gn >= NN) gn = NN - 1;
            cpa16(ah + r * PPIT + q * 16, &xh4[gn * 8 + q]);
            cpa16(al + r * PPIT + q * 16, &xl4[gn * 8 + q]);
        }
    };

    int sel = 0;
    if (blockIdx.x < ntiles) stageA(Abuf[0], blockIdx.x * 128);
    CPA_COMMIT();

    for (int tile = blockIdx.x; tile < ntiles; tile += gridDim.x) {
        // stage NEXT tile into the other buffer (overlaps this tile's mma)
        int nxt = tile + gridDim.x;
        if (nxt < ntiles) stageA(Abuf[sel ^ 1], nxt * 128);
        CPA_COMMIT();
        CPA_WAIT1();          // current buffer's group complete
        __syncthreads();      // visible to all warps (also covers B on iter 0)

        const uint32_t aH = (uint32_t)__cvta_generic_to_shared(Abuf[sel]) + a_loff;
        const uint32_t aL = aH + 128 * PPIT;
        const int base = tile * 128;

        float C[16][4];
        #pragma unroll
        for (int nt = 0; nt < 16; nt++) {
            C[nt][0] = 0.f; C[nt][1] = 0.f; C[nt][2] = 0.f; C[nt][3] = 0.f;
        }

        #pragma unroll
        for (int ks = 0; ks < 4; ks++) {
            unsigned Ah[4], Al4[4];
            ldsm4(Ah[0], Ah[1], Ah[2], Ah[3], aH + ks * 32);
            ldsm4(Al4[0], Al4[1], Al4[2], Al4[3], aL + ks * 32);
            #pragma unroll
            for (int ntp = 0; ntp < 8; ntp++) {
                unsigned Bh[4], Bl[4];
                ldsm4(Bh[0], Bh[1], Bh[2], Bh[3], bH + ntp * 16 * PPIT + ks * 32);
                ldsm4(Bl[0], Bl[1], Bl[2], Bl[3], bL + ntp * 16 * PPIT + ks * 32);
                mma16816(C[2 * ntp],     Ah,  Bh);
                mma16816(C[2 * ntp],     Ah,  Bl);
                mma16816(C[2 * ntp],     Al4, Bh);
                mma16816(C[2 * ntp + 1], Ah,  Bh + 2);
                mma16816(C[2 * ntp + 1], Ah,  Bl + 2);
                mma16816(C[2 * ntp + 1], Al4, Bh + 2);
            }
        }
        __syncthreads();      // all reads of Abuf[sel] done before it is restaged

        int r0 = base + (w << 4) + (l >> 2);
        int r1 = r0 + 8;
        int cc = (l & 3) * 2;
        #pragma unroll
        for (int nt = 0; nt < 8; nt++) {
            int col = nt * 8 + cc;
            if (r0 < NN) *(float2*)(g_p1 + (size_t)r0 * H + col) = make_float2(C[nt][0], C[nt][1]);
            if (r1 < NN) *(float2*)(g_p1 + (size_t)r1 * H + col) = make_float2(C[nt][2], C[nt][3]);
        }
        #pragma unroll
        for (int nt = 8; nt < 16; nt++) {
            int col = (nt - 8) * 8 + cc;
            float2 bb = bias2[nt - 8];
            if (r0 < NN) *(float2*)(g_p2 + (size_t)r0 * H + col) =
                make_float2(C[nt][0] + bb.x, C[nt][1] + bb.y);
            if (r1 < NN) *(float2*)(g_p2 + (size_t)r1 * H + col) =
                make_float2(C[nt][2] + bb.x, C[nt][3] + bb.y);
        }
        sel ^= 1;
    }
}

// ---------- CSR edge pass (2-way unrolled): agg[n] -> bf16 hi/lo ----------
__global__ __launch_bounds__(NT) void k_edge() {
    int idx = blockIdx.x * NT + threadIdx.x;
    int n = idx >> 3, q = idx & 7;
    int s0 = g_off[n], s1 = g_off[n + 1];
    const float4* p2 = (const float4*)(g_p2 + (size_t)n * H) + q * 2;
    float4 b0 = p2[0], b1 = p2[1];
    float a[8] = {0.f, 0.f, 0.f, 0.f, 0.f, 0.f, 0.f, 0.f};
    int i = s0;
    for (; i + 2 <= s1; i += 2) {
        int src0 = g_csr[i], src1 = g_csr[i + 1];
        const float4* pa = (const float4*)(g_p1 + (size_t)src0 * H) + q * 2;
        const float4* pb = (const float4*)(g_p1 + (size_t)src1 * H) + q * 2;
        float4 c0 = pa[0], c1 = pa[1];
        float4 d0 = pb[0], d1 = pb[1];
        a[0] += fmaxf(c0.x + b0.x, 0.f) + fmaxf(d0.x + b0.x, 0.f);
        a[1] += fmaxf(c0.y + b0.y, 0.f) + fmaxf(d0.y + b0.y, 0.f);
        a[2] += fmaxf(c0.z + b0.z, 0.f) + fmaxf(d0.z + b0.z, 0.f);
        a[3] += fmaxf(c0.w + b0.w, 0.f) + fmaxf(d0.w + b0.w, 0.f);
        a[4] += fmaxf(c1.x + b1.x, 0.f) + fmaxf(d1.x + b1.x, 0.f);
        a[5] += fmaxf(c1.y + b1.y, 0.f) + fmaxf(d1.y + b1.y, 0.f);
        a[6] += fmaxf(c1.z + b1.z, 0.f) + fmaxf(d1.z + b1.z, 0.f);
        a[7] += fmaxf(c1.w + b1.w, 0.f) + fmaxf(d1.w + b1.w, 0.f);
    }
    if (i < s1) {
        int src = g_csr[i];
        const float4* p1 = (const float4*)(g_p1 + (size_t)src * H) + q * 2;
        float4 c0 = p1[0], c1 = p1[1];
        a[0] += fmaxf(c0.x + b0.x, 0.f); a[1] += fmaxf(c0.y + b0.y, 0.f);
        a[2] += fmaxf(c0.z + b0.z, 0.f); a[3] += fmaxf(c0.w + b0.w, 0.f);
        a[4] += fmaxf(c1.x + b1.x, 0.f); a[5] += fmaxf(c1.y + b1.y, 0.f);
        a[6] += fmaxf(c1.z + b1.z, 0.f); a[7] += fmaxf(c1.w + b1.w, 0.f);
    }
    float ic = 1.0f / fmaxf((float)(s1 - s0), 1.0f);
    __nv_bfloat162 h[4], lo[4];
    #pragma unroll
    for (int j = 0; j < 4; j++) split2(a[2 * j] * ic, a[2 * j + 1] * ic, h[j], lo[j]);
    *(uint4*)(g_ah + (size_t)n * 32 + q * 4) = *(uint4*)h;
    *(uint4*)(g_al + (size_t)n * 32 + q * 4) = *(uint4*)lo;
}

// ---------- tensor-core update + residual + LayerNorm ----------
__global__ __launch_bounds__(256, 2) void k_upd_t(int layer, const float* __restrict__ B,
                                                  const float* __restrict__ lng,
                                                  const float* __restrict__ lnb) {
    extern __shared__ char smc[];
    char* AH = smc;
    char* AL = AH + 128 * UPIT;
    char* BH = AL + 128 * UPIT;
    char* BL = BH + 64 * UPIT;
    float* prm = (float*)(BL + 64 * UPIT);

    const int tid = threadIdx.x;
    const int w = tid >> 5, l = tid & 31;

    {
        const uint4* sh = (const uint4*)(g_uh + layer * 64 * 136);
        const uint4* sl = (const uint4*)(g_ul + layer * 64 * 136);
        for (int i = tid; i < 1088; i += 256) {
            ((uint4*)BH)[i] = sh[i];
            ((uint4*)BL)[i] = sl[i];
        }
        if (tid < 64) {
            prm[tid] = B[tid];
            prm[64 + tid] = lng[tid];
            prm[128 + tid] = lnb[tid];
        }
    }

    const uint32_t a_loff = (uint32_t)(((w << 4) + (l & 15)) * UPIT) + ((l >> 4) ? 16u : 0u);
    const uint32_t b_loff = (uint32_t)((l & 7) * UPIT) + (((l >> 3) & 1) ? 16u : 0u)
                          + (((l >> 4) & 1) ? 8u * UPIT : 0u);
    const uint32_t aH = (uint32_t)__cvta_generic_to_shared(AH) + a_loff;
    const uint32_t aL = (uint32_t)__cvta_generic_to_shared(AL) + a_loff;
    const uint32_t bH = (uint32_t)__cvta_generic_to_shared(BH) + b_loff;
    const uint32_t bL = (uint32_t)__cvta_generic_to_shared(BL) + b_loff;

    const uint4* xh4 = (const uint4*)g_xh;
    const uint4* xl4 = (const uint4*)g_xl;
    const uint4* ah4 = (const uint4*)g_ah;
    const uint4* al4 = (const uint4*)g_al;

    const int ntiles = (NN + 127) / 128;

    auto stageA = [&](int base) {
        #pragma unroll
        for (int s = 0; s < 8; s++) {
            int i = s * 256 + tid;
            int r = i >> 4, q = i & 15;
            int gn = base + r; if (gn >= NN) gn = NN - 1;
            const uint4* srch = (q < 8) ? &xh4[gn * 8 + q] : &ah4[gn * 8 + (q - 8)];
            const uint4* srcl = (q < 8) ? &xl4[gn * 8 + q] : &al4[gn * 8 + (q - 8)];
            cpa16(AH + r * UPIT + q * 16, srch);
            cpa16(AL + r * UPIT + q * 16, srcl);
        }
    };

    if (blockIdx.x < ntiles) stageA(blockIdx.x * 128);
    CPA_COMMIT();

    for (int tile = blockIdx.x; tile < ntiles; tile += gridDim.x) {
        const int base = tile * 128;
        CPA_WAIT0();
        __syncthreads();

        float C[8][4];
        #pragma unroll
        for (int nt = 0; nt < 8; nt++) {
            C[nt][0] = 0.f; C[nt][1] = 0.f; C[nt][2] = 0.f; C[nt][3] = 0.f;
        }

        #pragma unroll
        for (int ks = 0; ks < 8; ks++) {
            unsigned Ah[4], Al4r[4];
            ldsm4(Ah[0], Ah[1], Ah[2], Ah[3], aH + ks * 32);
            ldsm4(Al4r[0], Al4r[1], Al4r[2], Al4r[3], aL + ks * 32);
            #pragma unroll
            for (int ntp = 0; ntp < 4; ntp++) {
                unsigned Bh[4], Bl[4];
                ldsm4(Bh[0], Bh[1], Bh[2], Bh[3], bH + ntp * 16 * UPIT + ks * 32);
                ldsm4(Bl[0], Bl[1], Bl[2], Bl[3], bL + ntp * 16 * UPIT + ks * 32);
                mma16816(C[2 * ntp],     Ah,   Bh);
                mma16816(C[2 * ntp],     Ah,   Bl);
                mma16816(C[2 * ntp],     Al4r, Bh);
                mma16816(C[2 * ntp + 1], Ah,   Bh + 2);
                mma16816(C[2 * ntp + 1], Ah,   Bl + 2);
                mma16816(C[2 * ntp + 1], Al4r, Bh + 2);
            }
        }
        __syncthreads();

        int nxt = tile + gridDim.x;
        if (nxt < ntiles) stageA(nxt * 128);
        CPA_COMMIT();

        // epilogue overlaps staging
        int rr0 = base + (w << 4) + (l >> 2);
        int rr1 = rr0 + 8;
        int r0c = rr0 < NN ? rr0 : NN - 1;
        int r1c = rr1 < NN ? rr1 : NN - 1;
        int cc = (l & 3) * 2;
        float h0[8], h1[8];
        float s1a = 0.f, s2a = 0.f, s1b = 0.f, s2b = 0.f;
        #pragma unroll
        for (int nt = 0; nt < 8; nt++) {
            int col = nt * 8 + cc;
            float bx = prm[col], by = prm[col + 1];
            float2 xa = *(const float2*)(g_x + (size_t)r0c * H + col);
            float2 xb = *(const float2*)(g_x + (size_t)r1c * H + col);
            float v0 = fmaxf(C[nt][0] + bx, 0.f) + xa.x;
            float v1 = fmaxf(C[nt][1] + by, 0.f) + xa.y;
            float v2 = fmaxf(C[nt][2] + bx, 0.f) + xb.x;
            float v3 = fmaxf(C[nt][3] + by, 0.f) + xb.y;
            h0[nt] = v0; h1[nt] = v2;
            s1a += v0 + v1; s2a += v0 * v0 + v1 * v1;
            s1b += v2 + v3; s2b += v2 * v2 + v3 * v3;
            C[nt][1] = v1; C[nt][3] = v3;
        }
        #pragma unroll
        for (int d = 1; d < 4; d <<= 1) {
            s1a += __shfl_xor_sync(0xFFFFFFFFu, s1a, d);
            s2a += __shfl_xor_sync(0xFFFFFFFFu, s2a, d);
            s1b += __shfl_xor_sync(0xFFFFFFFFu, s1b, d);
            s2b += __shfl_xor_sync(0xFFFFFFFFu, s2b, d);
        }
        float mua = s1a * 0.015625f, mub = s1b * 0.015625f;
        float sca = rsqrtf(fmaxf(s2a * 0.015625f - mua * mua, 0.f) + 1e-5f);
        float scb = rsqrtf(fmaxf(s2b * 0.015625f - mub * mub, 0.f) + 1e-5f);
        #pragma unroll
        for (int nt = 0; nt < 8; nt++) {
            int col = nt * 8 + cc;
            float gx = prm[64 + col], gy = prm[65 + col];
            float bx = prm[128 + col], by = prm[129 + col];
            if (rr0 < NN) {
                float o0 = (h0[nt] - mua) * sca * gx + bx;
                float o1 = (C[nt][1] - mua) * sca * gy + by;
                *(float2*)(g_x + (size_t)rr0 * H + col) = make_float2(o0, o1);
                __nv_bfloat162 hh, ll;
                split2(o0, o1, hh, ll);
                g_xh[(size_t)rr0 * 32 + (col >> 1)] = hh;
                g_xl[(size_t)rr0 * 32 + (col >> 1)] = ll;
            }
            if (rr1 < NN) {
                float o2 = (h1[nt] - mub) * scb * gx + bx;
                float o3 = (C[nt][3] - mub) * scb * gy + by;
                *(float2*)(g_x + (size_t)rr1 * H + col) = make_float2(o2, o3);
                __nv_bfloat162 hh, ll;
                split2(o2, o3, hh, ll);
                g_xh[(size_t)rr1 * 32 + (col >> 1)] = hh;
                g_xl[(size_t)rr1 * 32 + (col >> 1)] = ll;
            }
        }
    }
}

// ---------- final mean/max over nodes ----------
__global__ void k_reduce() {
    __shared__ float rs[4][64];
    __shared__ float rm[4][64];
    int j = threadIdx.x & 63, g = threadIdx.x >> 6;
    float s = 0.f, m = -3.402823466e38f;
    for (int n = blockIdx.x * 4 + g; n < NN; n += gridDim.x * 4) {
        float v = g_x[(size_t)n * H + j];
        s += v; m = fmaxf(m, v);
    }
    rs[g][j] = s; rm[g][j] = m;
    __syncthreads();
    if (g == 0) {
        #pragma unroll
        for (int i = 1; i < 4; i++) { s += rs[i][j]; m = fmaxf(m, rm[i][j]); }
        atomicAdd(&g_sum[j], s);
        atomicMax(&g_maxb[j], encf(m));
    }
}

__global__ void k_final(float* out) {
    int t = threadIdx.x;
    if (t < 64) out[t] = g_sum[t] * (1.0f / NN);
    else        out[t] = decf(g_maxb[t - 64]);
}

// ---------- launch ----------
extern "C" void kernel_launch(void* const* d_in, const int* in_sizes, int n_in,
                              void* d_out, int out_size) {
    const int*   ti    = (const int*)d_in[0];
    const int*   edges = (const int*)d_in[1];
    const float* et    = (const float*)d_in[2];
    const float* msg_w = (const float*)d_in[3];
    const float* msg_b = (const float*)d_in[4];
    const float* upd_w = (const float*)d_in[5];
    const float* upd_b = (const float*)d_in[6];
    const float* lng   = (const float*)d_in[7];
    const float* lnb   = (const float*)d_in[8];
    float* out = (float*)d_out;

    cudaFuncSetAttribute(k_proj_t, cudaFuncAttributeMaxDynamicSharedMemorySize, SMEM_PROJT);
    cudaFuncSetAttribute(k_upd_t,  cudaFuncAttributeMaxDynamicSharedMemorySize, SMEM_UPDT);

    k_setup<<<512, 256>>>(ti, et, edges, msg_w, upd_w);
    k_hist<<<512, 256>>>(edges);
    k_scan1<<<NBLK, 256>>>();
    // layer-0 proj placed 4th so ncu (-s5 -c1) profiles it
    k_proj_t<<<296, 256, SMEM_PROJT>>>(0, msg_b);
    k_scan2<<<1, 512>>>();
    k_scan3<<<392, 256>>>();
    k_scatter<<<(NE + 255) / 256, 256>>>(edges);

    for (int l = 0; l < 3; l++) {
        if (l > 0) k_proj_t<<<296, 256, SMEM_PROJT>>>(l, msg_b + l * 64);
        k_edge<<<NN * 8 / NT, NT>>>();
        k_upd_t<<<296, 256, SMEM_UPDT>>>(l, upd_b + l * 64, lng + l * 64, lnb + l * 64);
    }

    k_reduce<<<296, 256>>>();
    k_final<<<1, 128>>>(out);
}

// round 13
// speedup vs baseline: 1.0848x; 1.0848x over previous
#include <cuda_runtime.h>
#include <cuda_bf16.h>
#include <cstdint>

#define NN 100000
#define NE 800000
#define H  64
#define NT 256
#define NBLK 391
#define PPIT 144   // proj smem row pitch bytes (72 bf16)
#define UPIT 272   // upd smem row pitch bytes (136 bf16)

#define SMEM_PROJT (4 * 128 * PPIT)                          // AH AL BH BL
#define SMEM_UPDT  (2 * 128 * UPIT + 2 * 64 * UPIT + 1280)   // AH AL BH BL + params + final acc

// Scratch (device globals: allocation-free rule)
__device__ __align__(16) float g_x[(size_t)NN * H];
__device__ __align__(16) float g_p1[(size_t)NN * H];
__device__ __align__(16) float g_p2[(size_t)NN * H];
__device__ __align__(16) __nv_bfloat162 g_xh[(size_t)NN * 32];
__device__ __align__(16) __nv_bfloat162 g_xl[(size_t)NN * 32];
__device__ __align__(16) __nv_bfloat162 g_ah[(size_t)NN * 32];
__device__ __align__(16) __nv_bfloat162 g_al[(size_t)NN * 32];
__device__ __align__(16) __nv_bfloat16 g_bh[3 * 128 * 72];   // proj W hi [C][k] pitch 72
__device__ __align__(16) __nv_bfloat16 g_bl[3 * 128 * 72];
__device__ __align__(16) __nv_bfloat16 g_uh[3 * 64 * 136];   // upd W hi [C][k] pitch 136
__device__ __align__(16) __nv_bfloat16 g_ul[3 * 64 * 136];
__device__ int g_deg[NN];
__device__ int g_off[NN + 1];
__device__ int g_cur[NN];
__device__ int g_csr[NE];
__device__ int g_bsum[NBLK];
__device__ int g_boff[NBLK];
__device__ float g_sum[H];
__device__ unsigned g_maxb[H];

// ---------- helpers ----------
__device__ __forceinline__ unsigned encf(float f) {
    unsigned u = __float_as_uint(f);
    return (u & 0x80000000u) ? ~u : (u | 0x80000000u);
}
__device__ __forceinline__ float decf(unsigned u) {
    return (u & 0x80000000u) ? __uint_as_float(u & 0x7FFFFFFFu) : __uint_as_float(~u);
}
__device__ __forceinline__ void split2(float a, float b, __nv_bfloat162& h, __nv_bfloat162& lo) {
    __nv_bfloat16 ha = __float2bfloat16(a), hb = __float2bfloat16(b);
    h = __halves2bfloat162(ha, hb);
    lo = __halves2bfloat162(__float2bfloat16(a - __bfloat162float(ha)),
                            __float2bfloat16(b - __bfloat162float(hb)));
}
__device__ __forceinline__ void ldsm4(unsigned& r0, unsigned& r1, unsigned& r2, unsigned& r3,
                                      uint32_t addr) {
    asm volatile("ldmatrix.sync.aligned.m8n8.x4.shared.b16 {%0,%1,%2,%3}, [%4];"
                 : "=r"(r0), "=r"(r1), "=r"(r2), "=r"(r3) : "r"(addr));
}
__device__ __forceinline__ void mma16816(float* c, const unsigned* a, const unsigned* b) {
    asm volatile("mma.sync.aligned.m16n8k16.row.col.f32.bf16.bf16.f32 "
                 "{%0,%1,%2,%3}, {%4,%5,%6,%7}, {%8,%9}, {%0,%1,%2,%3};"
                 : "+f"(c[0]), "+f"(c[1]), "+f"(c[2]), "+f"(c[3])
                 : "r"(a[0]), "r"(a[1]), "r"(a[2]), "r"(a[3]), "r"(b[0]), "r"(b[1]));
}
__device__ __forceinline__ void cpa16(void* dst, const void* src) {
    unsigned d = (unsigned)__cvta_generic_to_shared(dst);
    asm volatile("cp.async.ca.shared.global [%0], [%1], 16;" :: "r"(d), "l"(src));
}
#define CPA_COMMIT() asm volatile("cp.async.commit_group;")
#define CPA_WAIT0()  asm volatile("cp.async.wait_group 0;")

// ---------- merged setup: embed + hist + weight prepack ----------
__global__ void k_setup(const int* __restrict__ ti, const float* __restrict__ et,
                        const int* __restrict__ edges,
                        const float* __restrict__ msg_w, const float* __restrict__ upd_w) {
    int i = blockIdx.x * blockDim.x + threadIdx.x;
    int stride = gridDim.x * blockDim.x;
    for (int n = i; n < NN; n += stride) g_deg[n] = 0;
    if (i < H) { g_sum[i] = 0.f; g_maxb[i] = 0u; }
    for (int lin = i; lin < NN * 16; lin += stride) {
        int n = lin >> 4, q = lin & 15;
        float4 v = ((const float4*)et)[ti[n] * 16 + q];
        ((float4*)g_x)[lin] = v;
        __nv_bfloat162 h0, l0, h1, l1;
        split2(v.x, v.y, h0, l0);
        split2(v.z, v.w, h1, l1);
        g_xh[lin * 2] = h0; g_xh[lin * 2 + 1] = h1;
        g_xl[lin * 2] = l0; g_xl[lin * 2 + 1] = l1;
    }
    for (int idx = i; idx < 3 * 128 * 72; idx += stride) {
        int l = idx / (128 * 72), r = idx % (128 * 72);
        int C = r / 72, k = r % 72;
        __nv_bfloat16 h = __float2bfloat16(0.f), lo = h;
        if (k < 64) {
            float v = msg_w[l * 8192 + (k + (C & 64)) * 64 + (C & 63)];
            h = __float2bfloat16(v);
            lo = __float2bfloat16(v - __bfloat162float(h));
        }
        g_bh[idx] = h; g_bl[idx] = lo;
    }
    for (int idx = i; idx < 3 * 64 * 136; idx += stride) {
        int l = idx / (64 * 136), r = idx % (64 * 136);
        int C = r / 136, k = r % 136;
        __nv_bfloat16 h = __float2bfloat16(0.f), lo = h;
        if (k < 128) {
            float v = upd_w[l * 8192 + k * 64 + C];
            h = __float2bfloat16(v);
            lo = __float2bfloat16(v - __bfloat162float(h));
        }
        g_uh[idx] = h; g_ul[idx] = lo;
    }
    // histogram (device-wide atomics; g_deg zeroed above by this same grid only
    // if the zero pass covers all n before any atomic from another block —
    // so zero via a separate full pass first is unsafe; instead zero was done
    // grid-stride above but atomics below may race with zeroing of other blocks.
    // Use a grid-stride barrier-free approach: zeroing and atomics must not
    // overlap, so do hist in k_scan1's grid instead? Simpler: edges histogram
    // done here is UNSAFE. -> moved to k_hist below.
}

__global__ void k_hist(const int* __restrict__ edges) {
    int i = blockIdx.x * blockDim.x + threadIdx.x;
    int stride = gridDim.x * blockDim.x;
    for (int e = i; e < NE; e += stride)
        atomicAdd(&g_deg[((const int2*)edges)[e].y], 1);
}

// ---------- exclusive scan ----------
__global__ void k_scan1() {
    __shared__ int s[256];
    int t = threadIdx.x;
    int i = blockIdx.x * 256 + t;
    int v = (i < NN) ? g_deg[i] : 0;
    s[t] = v;
    __syncthreads();
    #pragma unroll
    for (int d = 1; d < 256; d <<= 1) {
        int tv = (t >= d) ? s[t - d] : 0;
        __syncthreads();
        s[t] += tv;
        __syncthreads();
    }
    if (i < NN) g_off[i] = s[t] - v;
    if (t == 255) g_bsum[blockIdx.x] = s[255];
}

__global__ void k_scan2() {
    __shared__ int s[512];
    int t = threadIdx.x;
    int v = (t < NBLK) ? g_bsum[t] : 0;
    s[t] = v;
    __syncthreads();
    #pragma unroll
    for (int d = 1; d < 512; d <<= 1) {
        int tv = (t >= d) ? s[t - d] : 0;
        __syncthreads();
        s[t] += tv;
        __syncthreads();
    }
    if (t < NBLK) g_boff[t] = s[t] - v;
}

__global__ void k_scan3() {
    int i = blockIdx.x * blockDim.x + threadIdx.x;
    if (i < NN) {
        int val = g_off[i] + g_boff[i >> 8];
        g_off[i] = val;
        g_cur[i] = val;
    }
    if (i == 0) g_off[NN] = NE;
}

__global__ void k_scatter(const int* __restrict__ edges) {
    int e = blockIdx.x * blockDim.x + threadIdx.x;
    if (e < NE) {
        int2 ed = ((const int2*)edges)[e];
        int pos = atomicAdd(&g_cur[ed.y], 1);
        g_csr[pos] = ed.x;
    }
}

// ---------- tensor-core projection (R11 pipeline: stage-next during epilogue) ----------
__global__ __launch_bounds__(256, 2) void k_proj_t(int layer, const float* __restrict__ msg_b) {
    extern __shared__ char smc[];
    char* AH = smc;
    char* AL = AH + 128 * PPIT;
    char* BH = AL + 128 * PPIT;
    char* BL = BH + 128 * PPIT;

    const int tid = threadIdx.x;
    const int w = tid >> 5, l = tid & 31;

    {
        const uint4* sh = (const uint4*)(g_bh + layer * 128 * 72);
        const uint4* sl = (const uint4*)(g_bl + layer * 128 * 72);
        for (int i = tid; i < 1152; i += 256) {
            ((uint4*)BH)[i] = sh[i];
            ((uint4*)BL)[i] = sl[i];
        }
    }
    float2 bias2[8];
    #pragma unroll
    for (int i = 0; i < 8; i++) bias2[i] = *(const float2*)(msg_b + i * 8 + (l & 3) * 2);

    const uint32_t a_loff = (uint32_t)(((w << 4) + (l & 15)) * PPIT) + ((l >> 4) ? 16u : 0u);
    const uint32_t b_loff = (uint32_t)((l & 7) * PPIT) + (((l >> 3) & 1) ? 16u : 0u)
                          + (((l >> 4) & 1) ? 8u * PPIT : 0u);
    const uint32_t aH = (uint32_t)__cvta_generic_to_shared(AH) + a_loff;
    const uint32_t aL = (uint32_t)__cvta_generic_to_shared(AL) + a_loff;
    const uint32_t bH = (uint32_t)__cvta_generic_to_shared(BH) + b_loff;
    const uint32_t bL = (uint32_t)__cvta_generic_to_shared(BL) + b_loff;

    const uint4* xh4 = (const uint4*)g_xh;
    const uint4* xl4 = (const uint4*)g_xl;

    const int ntiles = (NN + 127) / 128;

    auto stageA = [&](int base) {
        #pragma unroll
        for (int s = 0; s < 4; s++) {
            int i = s * 256 + tid;
            int r = i >> 3, q = i & 7;
            int gn = base + r; if (gn >= NN) gn = NN - 1;
            cpa16(AH + r * PPIT + q * 16, &xh4[gn * 8 + q]);
            cpa16(AL + r * PPIT + q * 16, &xl4[gn * 8 + q]);
        }
    };

    if (blockIdx.x < ntiles) stageA(blockIdx.x * 128);
    CPA_COMMIT();

    for (int tile = blockIdx.x; tile < ntiles; tile += gridDim.x) {
        const int base = tile * 128;
        CPA_WAIT0();
        __syncthreads();

        float C[16][4];
        #pragma unroll
        for (int nt = 0; nt < 16; nt++) {
            C[nt][0] = 0.f; C[nt][1] = 0.f; C[nt][2] = 0.f; C[nt][3] = 0.f;
        }

        #pragma unroll
        for (int ks = 0; ks < 4; ks++) {
            unsigned Ah[4], Al4[4];
            ldsm4(Ah[0], Ah[1], Ah[2], Ah[3], aH + ks * 32);
            ldsm4(Al4[0], Al4[1], Al4[2], Al4[3], aL + ks * 32);
            #pragma unroll
            for (int ntp = 0; ntp < 8; ntp++) {
                unsigned Bh[4], Bl[4];
                ldsm4(Bh[0], Bh[1], Bh[2], Bh[3], bH + ntp * 16 * PPIT + ks * 32);
                ldsm4(Bl[0], Bl[1], Bl[2], Bl[3], bL + ntp * 16 * PPIT + ks * 32);
                mma16816(C[2 * ntp],     Ah,  Bh);
                mma16816(C[2 * ntp],     Ah,  Bl);
                mma16816(C[2 * ntp],     Al4, Bh);
                mma16816(C[2 * ntp + 1], Ah,  Bh + 2);
                mma16816(C[2 * ntp + 1], Ah,  Bl + 2);
                mma16816(C[2 * ntp + 1], Al4, Bh + 2);
            }
        }
        __syncthreads();

        int nxt = tile + gridDim.x;
        if (nxt < ntiles) stageA(nxt * 128);
        CPA_COMMIT();

        int r0 = base + (w << 4) + (l >> 2);
        int r1 = r0 + 8;
        int cc = (l & 3) * 2;
        #pragma unroll
        for (int nt = 0; nt < 8; nt++) {
            int col = nt * 8 + cc;
            if (r0 < NN) *(float2*)(g_p1 + (size_t)r0 * H + col) = make_float2(C[nt][0], C[nt][1]);
            if (r1 < NN) *(float2*)(g_p1 + (size_t)r1 * H + col) = make_float2(C[nt][2], C[nt][3]);
        }
        #pragma unroll
        for (int nt = 8; nt < 16; nt++) {
            int col = (nt - 8) * 8 + cc;
            float2 bb = bias2[nt - 8];
            if (r0 < NN) *(float2*)(g_p2 + (size_t)r0 * H + col) =
                make_float2(C[nt][0] + bb.x, C[nt][1] + bb.y);
            if (r1 < NN) *(float2*)(g_p2 + (size_t)r1 * H + col) =
                make_float2(C[nt][2] + bb.x, C[nt][3] + bb.y);
        }
    }
}

// ---------- CSR edge pass (2-way unrolled): agg[n] -> bf16 hi/lo ----------
__global__ __launch_bounds__(NT) void k_edge() {
    int idx = blockIdx.x * NT + threadIdx.x;
    int n = idx >> 3, q = idx & 7;
    int s0 = g_off[n], s1 = g_off[n + 1];
    const float4* p2 = (const float4*)(g_p2 + (size_t)n * H) + q * 2;
    float4 b0 = p2[0], b1 = p2[1];
    float a[8] = {0.f, 0.f, 0.f, 0.f, 0.f, 0.f, 0.f, 0.f};
    int i = s0;
    for (; i + 2 <= s1; i += 2) {
        int src0 = g_csr[i], src1 = g_csr[i + 1];
        const float4* pa = (const float4*)(g_p1 + (size_t)src0 * H) + q * 2;
        const float4* pb = (const float4*)(g_p1 + (size_t)src1 * H) + q * 2;
        float4 c0 = pa[0], c1 = pa[1];
        float4 d0 = pb[0], d1 = pb[1];
        a[0] += fmaxf(c0.x + b0.x, 0.f) + fmaxf(d0.x + b0.x, 0.f);
        a[1] += fmaxf(c0.y + b0.y, 0.f) + fmaxf(d0.y + b0.y, 0.f);
        a[2] += fmaxf(c0.z + b0.z, 0.f) + fmaxf(d0.z + b0.z, 0.f);
        a[3] += fmaxf(c0.w + b0.w, 0.f) + fmaxf(d0.w + b0.w, 0.f);
        a[4] += fmaxf(c1.x + b1.x, 0.f) + fmaxf(d1.x + b1.x, 0.f);
        a[5] += fmaxf(c1.y + b1.y, 0.f) + fmaxf(d1.y + b1.y, 0.f);
        a[6] += fmaxf(c1.z + b1.z, 0.f) + fmaxf(d1.z + b1.z, 0.f);
        a[7] += fmaxf(c1.w + b1.w, 0.f) + fmaxf(d1.w + b1.w, 0.f);
    }
    if (i < s1) {
        int src = g_csr[i];
        const float4* p1 = (const float4*)(g_p1 + (size_t)src * H) + q * 2;
        float4 c0 = p1[0], c1 = p1[1];
        a[0] += fmaxf(c0.x + b0.x, 0.f); a[1] += fmaxf(c0.y + b0.y, 0.f);
        a[2] += fmaxf(c0.z + b0.z, 0.f); a[3] += fmaxf(c0.w + b0.w, 0.f);
        a[4] += fmaxf(c1.x + b1.x, 0.f); a[5] += fmaxf(c1.y + b1.y, 0.f);
        a[6] += fmaxf(c1.z + b1.z, 0.f); a[7] += fmaxf(c1.w + b1.w, 0.f);
    }
    float ic = 1.0f / fmaxf((float)(s1 - s0), 1.0f);
    __nv_bfloat162 h[4], lo[4];
    #pragma unroll
    for (int j = 0; j < 4; j++) split2(a[2 * j] * ic, a[2 * j + 1] * ic, h[j], lo[j]);
    *(uint4*)(g_ah + (size_t)n * 32 + q * 4) = *(uint4*)h;
    *(uint4*)(g_al + (size_t)n * 32 + q * 4) = *(uint4*)lo;
}

// ---------- tensor-core update + residual + LayerNorm (+fused final reduce) ----------
template <bool FINAL>
__global__ __launch_bounds__(256, 2) void k_upd_t(int layer, const float* __restrict__ B,
                                                  const float* __restrict__ lng,
                                                  const float* __restrict__ lnb) {
    extern __shared__ char smc[];
    char* AH = smc;
    char* AL = AH + 128 * UPIT;
    char* BH = AL + 128 * UPIT;
    char* BL = BH + 64 * UPIT;
    float* prm = (float*)(BL + 64 * UPIT);           // bias[64], g[64], b2[64]
    float* fsum = prm + 192;                          // 64 (FINAL)
    unsigned* fmax = (unsigned*)(fsum + 64);          // 64 (FINAL)

    const int tid = threadIdx.x;
    const int w = tid >> 5, l = tid & 31;

    {
        const uint4* sh = (const uint4*)(g_uh + layer * 64 * 136);
        const uint4* sl = (const uint4*)(g_ul + layer * 64 * 136);
        for (int i = tid; i < 1088; i += 256) {
            ((uint4*)BH)[i] = sh[i];
            ((uint4*)BL)[i] = sl[i];
        }
        if (tid < 64) {
            prm[tid] = B[tid];
            prm[64 + tid] = lng[tid];
            prm[128 + tid] = lnb[tid];
            if (FINAL) { fsum[tid] = 0.f; fmax[tid] = 0u; }
        }
    }

    const uint32_t a_loff = (uint32_t)(((w << 4) + (l & 15)) * UPIT) + ((l >> 4) ? 16u : 0u);
    const uint32_t b_loff = (uint32_t)((l & 7) * UPIT) + (((l >> 3) & 1) ? 16u : 0u)
                          + (((l >> 4) & 1) ? 8u * UPIT : 0u);
    const uint32_t aH = (uint32_t)__cvta_generic_to_shared(AH) + a_loff;
    const uint32_t aL = (uint32_t)__cvta_generic_to_shared(AL) + a_loff;
    const uint32_t bH = (uint32_t)__cvta_generic_to_shared(BH) + b_loff;
    const uint32_t bL = (uint32_t)__cvta_generic_to_shared(BL) + b_loff;

    const uint4* xh4 = (const uint4*)g_xh;
    const uint4* xl4 = (const uint4*)g_xl;
    const uint4* ah4 = (const uint4*)g_ah;
    const uint4* al4 = (const uint4*)g_al;

    const int ntiles = (NN + 127) / 128;

    auto stageA = [&](int base) {
        #pragma unroll
        for (int s = 0; s < 8; s++) {
            int i = s * 256 + tid;
            int r = i >> 4, q = i & 15;
            int gn = base + r; if (gn >= NN) gn = NN - 1;
            const uint4* srch = (q < 8) ? &xh4[gn * 8 + q] : &ah4[gn * 8 + (q - 8)];
            const uint4* srcl = (q < 8) ? &xl4[gn * 8 + q] : &al4[gn * 8 + (q - 8)];
            cpa16(AH + r * UPIT + q * 16, srch);
            cpa16(AL + r * UPIT + q * 16, srcl);
        }
    };

    // per-thread final accumulators (columns nt*8+cc, nt*8+cc+1)
    float ls[16], lm[16];
    if (FINAL) {
        #pragma unroll
        for (int i = 0; i < 16; i++) { ls[i] = 0.f; lm[i] = -3.402823466e38f; }
    }

    if (blockIdx.x < ntiles) stageA(blockIdx.x * 128);
    CPA_COMMIT();

    for (int tile = blockIdx.x; tile < ntiles; tile += gridDim.x) {
        const int base = tile * 128;
        CPA_WAIT0();
        __syncthreads();

        float C[8][4];
        #pragma unroll
        for (int nt = 0; nt < 8; nt++) {
            C[nt][0] = 0.f; C[nt][1] = 0.f; C[nt][2] = 0.f; C[nt][3] = 0.f;
        }

        #pragma unroll
        for (int ks = 0; ks < 8; ks++) {
            unsigned Ah[4], Al4r[4];
            ldsm4(Ah[0], Ah[1], Ah[2], Ah[3], aH + ks * 32);
            ldsm4(Al4r[0], Al4r[1], Al4r[2], Al4r[3], aL + ks * 32);
            #pragma unroll
            for (int ntp = 0; ntp < 4; ntp++) {
                unsigned Bh[4], Bl[4];
                ldsm4(Bh[0], Bh[1], Bh[2], Bh[3], bH + ntp * 16 * UPIT + ks * 32);
                ldsm4(Bl[0], Bl[1], Bl[2], Bl[3], bL + ntp * 16 * UPIT + ks * 32);
                mma16816(C[2 * ntp],     Ah,   Bh);
                mma16816(C[2 * ntp],     Ah,   Bl);
                mma16816(C[2 * ntp],     Al4r, Bh);
                mma16816(C[2 * ntp + 1], Ah,   Bh + 2);
                mma16816(C[2 * ntp + 1], Ah,   Bl + 2);
                mma16816(C[2 * ntp + 1], Al4r, Bh + 2);
            }
        }
        __syncthreads();

        int nxt = tile + gridDim.x;
        if (nxt < ntiles) stageA(nxt * 128);
        CPA_COMMIT();

        // epilogue (overlaps staging)
        int rr0 = base + (w << 4) + (l >> 2);
        int rr1 = rr0 + 8;
        int r0c = rr0 < NN ? rr0 : NN - 1;
        int r1c = rr1 < NN ? rr1 : NN - 1;
        int cc = (l & 3) * 2;
        float h0[8], h1[8];
        float s1a = 0.f, s2a = 0.f, s1b = 0.f, s2b = 0.f;
        #pragma unroll
        for (int nt = 0; nt < 8; nt++) {
            int col = nt * 8 + cc;
            float bx = prm[col], by = prm[col + 1];
            float2 xa = *(const float2*)(g_x + (size_t)r0c * H + col);
            float2 xb = *(const float2*)(g_x + (size_t)r1c * H + col);
            float v0 = fmaxf(C[nt][0] + bx, 0.f) + xa.x;
            float v1 = fmaxf(C[nt][1] + by, 0.f) + xa.y;
            float v2 = fmaxf(C[nt][2] + bx, 0.f) + xb.x;
            float v3 = fmaxf(C[nt][3] + by, 0.f) + xb.y;
            h0[nt] = v0; h1[nt] = v2;
            s1a += v0 + v1; s2a += v0 * v0 + v1 * v1;
            s1b += v2 + v3; s2b += v2 * v2 + v3 * v3;
            C[nt][1] = v1; C[nt][3] = v3;
        }
        #pragma unroll
        for (int d = 1; d < 4; d <<= 1) {
            s1a += __shfl_xor_sync(0xFFFFFFFFu, s1a, d);
            s2a += __shfl_xor_sync(0xFFFFFFFFu, s2a, d);
            s1b += __shfl_xor_sync(0xFFFFFFFFu, s1b, d);
            s2b += __shfl_xor_sync(0xFFFFFFFFu, s2b, d);
        }
        float mua = s1a * 0.015625f, mub = s1b * 0.015625f;
        float sca = rsqrtf(fmaxf(s2a * 0.015625f - mua * mua, 0.f) + 1e-5f);
        float scb = rsqrtf(fmaxf(s2b * 0.015625f - mub * mub, 0.f) + 1e-5f);
        #pragma unroll
        for (int nt = 0; nt < 8; nt++) {
            int col = nt * 8 + cc;
            float gx = prm[64 + col], gy = prm[65 + col];
            float bx = prm[128 + col], by = prm[129 + col];
            if (rr0 < NN) {
                float o0 = (h0[nt] - mua) * sca * gx + bx;
                float o1 = (C[nt][1] - mua) * sca * gy + by;
                if (FINAL) {
                    ls[2 * nt] += o0; ls[2 * nt + 1] += o1;
                    lm[2 * nt] = fmaxf(lm[2 * nt], o0);
                    lm[2 * nt + 1] = fmaxf(lm[2 * nt + 1], o1);
                } else {
                    *(float2*)(g_x + (size_t)rr0 * H + col) = make_float2(o0, o1);
                    __nv_bfloat162 hh, ll;
                    split2(o0, o1, hh, ll);
                    g_xh[(size_t)rr0 * 32 + (col >> 1)] = hh;
                    g_xl[(size_t)rr0 * 32 + (col >> 1)] = ll;
                }
            }
            if (rr1 < NN) {
                float o2 = (h1[nt] - mub) * scb * gx + bx;
                float o3 = (C[nt][3] - mub) * scb * gy + by;
                if (FINAL) {
                    ls[2 * nt] += o2; ls[2 * nt + 1] += o3;
                    lm[2 * nt] = fmaxf(lm[2 * nt], o2);
                    lm[2 * nt + 1] = fmaxf(lm[2 * nt + 1], o3);
                } else {
                    *(float2*)(g_x + (size_t)rr1 * H + col) = make_float2(o2, o3);
                    __nv_bfloat162 hh, ll;
                    split2(o2, o3, hh, ll);
                    g_xh[(size_t)rr1 * 32 + (col >> 1)] = hh;
                    g_xl[(size_t)rr1 * 32 + (col >> 1)] = ll;
                }
            }
        }
    }

    if (FINAL) {
        int cc = (l & 3) * 2;
        __syncthreads();   // fsum/fmax init (tid<64) complete before atomics
        #pragma unroll
        for (int nt = 0; nt < 8; nt++) {
            int col = nt * 8 + cc;
            atomicAdd(&fsum[col], ls[2 * nt]);
            atomicAdd(&fsum[col + 1], ls[2 * nt + 1]);
            atomicMax(&fmax[col], encf(lm[2 * nt]));
            atomicMax(&fmax[col + 1], encf(lm[2 * nt + 1]));
        }
        __syncthreads();
        if (tid < 64) {
            atomicAdd(&g_sum[tid], fsum[tid]);
            atomicMax(&g_maxb[tid], fmax[tid]);
        }
    }
}

__global__ void k_final(float* out) {
    int t = threadIdx.x;
    if (t < 64) out[t] = g_sum[t] * (1.0f / NN);
    else        out[t] = decf(g_maxb[t - 64]);
}

// ---------- launch ----------
extern "C" void kernel_launch(void* const* d_in, const int* in_sizes, int n_in,
                              void* d_out, int out_size) {
    const int*   ti    = (const int*)d_in[0];
    const int*   edges = (const int*)d_in[1];
    const float* et    = (const float*)d_in[2];
    const float* msg_w = (const float*)d_in[3];
    const float* msg_b = (const float*)d_in[4];
    const float* upd_w = (const float*)d_in[5];
    const float* upd_b = (const float*)d_in[6];
    const float* lng   = (const float*)d_in[7];
    const float* lnb   = (const float*)d_in[8];
    float* out = (float*)d_out;

    cudaFuncSetAttribute(k_proj_t, cudaFuncAttributeMaxDynamicSharedMemorySize, SMEM_PROJT);
    cudaFuncSetAttribute(k_upd_t<false>, cudaFuncAttributeMaxDynamicSharedMemorySize, SMEM_UPDT);
    cudaFuncSetAttribute(k_upd_t<true>,  cudaFuncAttributeMaxDynamicSharedMemorySize, SMEM_UPDT);

    k_setup<<<512, 256>>>(ti, et, edges, msg_w, upd_w);
    k_hist<<<512, 256>>>(edges);
    k_scan1<<<NBLK, 256>>>();
    // layer-0 proj placed 4th so ncu (-s5 -c1) profiles it
    k_proj_t<<<296, 256, SMEM_PROJT>>>(0, msg_b);
    k_scan2<<<1, 512>>>();
    k_scan3<<<392, 256>>>();
    k_scatter<<<(NE + 255) / 256, 256>>>(edges);

    for (int l = 0; l < 3; l++) {
        if (l > 0) k_proj_t<<<296, 256, SMEM_PROJT>>>(l, msg_b + l * 64);
        k_edge<<<NN * 8 / NT, NT>>>();
        if (l < 2)
            k_upd_t<false><<<296, 256, SMEM_UPDT>>>(l, upd_b + l * 64, lng + l * 64, lnb + l * 64);
        else
            k_upd_t<true><<<296, 256, SMEM_UPDT>>>(l, upd_b + l * 64, lng + l * 64, lnb + l * 64);
    }

    k_final<<<1, 128>>>(out);
}

// round 14
// speedup vs baseline: 1.1872x; 1.0944x over previous
#include <cuda_runtime.h>
#include <cuda_bf16.h>
#include <cstdint>

#define NN 100000
#define NE 800000
#define H  64
#define NT 256
#define NBLK 391
#define PPIT 144   // proj smem row pitch bytes (72 bf16)
#define UPIT 272   // upd smem row pitch bytes (136 bf16)

#define SMEM_PROJT (4 * 128 * PPIT)                          // AH AL BH BL
#define SMEM_UPDT  (2 * 128 * UPIT + 2 * 64 * UPIT + 1280)   // AH AL BH BL + params + final acc

// Scratch (device globals: allocation-free rule)
__device__ __align__(16) float g_p1[(size_t)NN * H];
__device__ __align__(16) float g_p2[(size_t)NN * H];
__device__ __align__(16) __nv_bfloat162 g_xh[(size_t)NN * 32];
__device__ __align__(16) __nv_bfloat162 g_xl[(size_t)NN * 32];
__device__ __align__(16) __nv_bfloat162 g_ah[(size_t)NN * 32];
__device__ __align__(16) __nv_bfloat162 g_al[(size_t)NN * 32];
__device__ __align__(16) __nv_bfloat16 g_bh[3 * 128 * 72];   // proj W hi [C][k] pitch 72
__device__ __align__(16) __nv_bfloat16 g_bl[3 * 128 * 72];
__device__ __align__(16) __nv_bfloat16 g_uh[3 * 64 * 136];   // upd W hi [C][k] pitch 136
__device__ __align__(16) __nv_bfloat16 g_ul[3 * 64 * 136];
__device__ int g_deg[NN];
__device__ int g_off[NN + 1];
__device__ int g_cur[NN];
__device__ int g_csr[NE];
__device__ int g_bsum[NBLK];
__device__ int g_boff[NBLK];
__device__ float g_sum[H];
__device__ unsigned g_maxb[H];

// ---------- helpers ----------
__device__ __forceinline__ unsigned encf(float f) {
    unsigned u = __float_as_uint(f);
    return (u & 0x80000000u) ? ~u : (u | 0x80000000u);
}
__device__ __forceinline__ float decf(unsigned u) {
    return (u & 0x80000000u) ? __uint_as_float(u & 0x7FFFFFFFu) : __uint_as_float(~u);
}
__device__ __forceinline__ void split2(float a, float b, __nv_bfloat162& h, __nv_bfloat162& lo) {
    __nv_bfloat16 ha = __float2bfloat16(a), hb = __float2bfloat16(b);
    h = __halves2bfloat162(ha, hb);
    lo = __halves2bfloat162(__float2bfloat16(a - __bfloat162float(ha)),
                            __float2bfloat16(b - __bfloat162float(hb)));
}
__device__ __forceinline__ void ldsm4(unsigned& r0, unsigned& r1, unsigned& r2, unsigned& r3,
                                      uint32_t addr) {
    asm volatile("ldmatrix.sync.aligned.m8n8.x4.shared.b16 {%0,%1,%2,%3}, [%4];"
                 : "=r"(r0), "=r"(r1), "=r"(r2), "=r"(r3) : "r"(addr));
}
__device__ __forceinline__ void mma16816(float* c, const unsigned* a, const unsigned* b) {
    asm volatile("mma.sync.aligned.m16n8k16.row.col.f32.bf16.bf16.f32 "
                 "{%0,%1,%2,%3}, {%4,%5,%6,%7}, {%8,%9}, {%0,%1,%2,%3};"
                 : "+f"(c[0]), "+f"(c[1]), "+f"(c[2]), "+f"(c[3])
                 : "r"(a[0]), "r"(a[1]), "r"(a[2]), "r"(a[3]), "r"(b[0]), "r"(b[1]));
}
__device__ __forceinline__ void cpa16(void* dst, const void* src) {
    unsigned d = (unsigned)__cvta_generic_to_shared(dst);
    asm volatile("cp.async.ca.shared.global [%0], [%1], 16;" :: "r"(d), "l"(src));
}
#define CPA_COMMIT() asm volatile("cp.async.commit_group;")
#define CPA_WAIT0()  asm volatile("cp.async.wait_group 0;")

// ---------- merged setup: embed + weight prepack ----------
__global__ void k_setup(const int* __restrict__ ti, const float* __restrict__ et,
                        const float* __restrict__ msg_w, const float* __restrict__ upd_w) {
    int i = blockIdx.x * blockDim.x + threadIdx.x;
    int stride = gridDim.x * blockDim.x;
    for (int n = i; n < NN; n += stride) g_deg[n] = 0;
    if (i < H) { g_sum[i] = 0.f; g_maxb[i] = 0u; }
    for (int lin = i; lin < NN * 16; lin += stride) {
        int n = lin >> 4, q = lin & 15;
        float4 v = ((const float4*)et)[ti[n] * 16 + q];
        __nv_bfloat162 h0, l0, h1, l1;
        split2(v.x, v.y, h0, l0);
        split2(v.z, v.w, h1, l1);
        g_xh[lin * 2] = h0; g_xh[lin * 2 + 1] = h1;
        g_xl[lin * 2] = l0; g_xl[lin * 2 + 1] = l1;
    }
    for (int idx = i; idx < 3 * 128 * 72; idx += stride) {
        int l = idx / (128 * 72), r = idx % (128 * 72);
        int C = r / 72, k = r % 72;
        __nv_bfloat16 h = __float2bfloat16(0.f), lo = h;
        if (k < 64) {
            float v = msg_w[l * 8192 + (k + (C & 64)) * 64 + (C & 63)];
            h = __float2bfloat16(v);
            lo = __float2bfloat16(v - __bfloat162float(h));
        }
        g_bh[idx] = h; g_bl[idx] = lo;
    }
    for (int idx = i; idx < 3 * 64 * 136; idx += stride) {
        int l = idx / (64 * 136), r = idx % (64 * 136);
        int C = r / 136, k = r % 136;
        __nv_bfloat16 h = __float2bfloat16(0.f), lo = h;
        if (k < 128) {
            float v = upd_w[l * 8192 + k * 64 + C];
            h = __float2bfloat16(v);
            lo = __float2bfloat16(v - __bfloat162float(h));
        }
        g_uh[idx] = h; g_ul[idx] = lo;
    }
}

__global__ void k_hist(const int* __restrict__ edges) {
    int i = blockIdx.x * blockDim.x + threadIdx.x;
    int stride = gridDim.x * blockDim.x;
    for (int e = i; e < NE; e += stride)
        atomicAdd(&g_deg[((const int2*)edges)[e].y], 1);
}

// ---------- exclusive scan ----------
__global__ void k_scan1() {
    __shared__ int s[256];
    int t = threadIdx.x;
    int i = blockIdx.x * 256 + t;
    int v = (i < NN) ? g_deg[i] : 0;
    s[t] = v;
    __syncthreads();
    #pragma unroll
    for (int d = 1; d < 256; d <<= 1) {
        int tv = (t >= d) ? s[t - d] : 0;
        __syncthreads();
        s[t] += tv;
        __syncthreads();
    }
    if (i < NN) g_off[i] = s[t] - v;
    if (t == 255) g_bsum[blockIdx.x] = s[255];
}

__global__ void k_scan2() {
    __shared__ int s[512];
    int t = threadIdx.x;
    int v = (t < NBLK) ? g_bsum[t] : 0;
    s[t] = v;
    __syncthreads();
    #pragma unroll
    for (int d = 1; d < 512; d <<= 1) {
        int tv = (t >= d) ? s[t - d] : 0;
        __syncthreads();
        s[t] += tv;
        __syncthreads();
    }
    if (t < NBLK) g_boff[t] = s[t] - v;
}

__global__ void k_scan3() {
    int i = blockIdx.x * blockDim.x + threadIdx.x;
    if (i < NN) {
        int val = g_off[i] + g_boff[i >> 8];
        g_off[i] = val;
        g_cur[i] = val;
    }
    if (i == 0) g_off[NN] = NE;
}

__global__ void k_scatter(const int* __restrict__ edges) {
    int e = blockIdx.x * blockDim.x + threadIdx.x;
    if (e < NE) {
        int2 ed = ((const int2*)edges)[e];
        int pos = atomicAdd(&g_cur[ed.y], 1);
        g_csr[pos] = ed.x;
    }
}

// ---------- tensor-core projection ----------
__global__ __launch_bounds__(256, 2) void k_proj_t(int layer, const float* __restrict__ msg_b) {
    extern __shared__ char smc[];
    char* AH = smc;
    char* AL = AH + 128 * PPIT;
    char* BH = AL + 128 * PPIT;
    char* BL = BH + 128 * PPIT;

    const int tid = threadIdx.x;
    const int w = tid >> 5, l = tid & 31;

    {
        const uint4* sh = (const uint4*)(g_bh + layer * 128 * 72);
        const uint4* sl = (const uint4*)(g_bl + layer * 128 * 72);
        for (int i = tid; i < 1152; i += 256) {
            ((uint4*)BH)[i] = sh[i];
            ((uint4*)BL)[i] = sl[i];
        }
    }
    float2 bias2[8];
    #pragma unroll
    for (int i = 0; i < 8; i++) bias2[i] = *(const float2*)(msg_b + i * 8 + (l & 3) * 2);

    const uint32_t a_loff = (uint32_t)(((w << 4) + (l & 15)) * PPIT) + ((l >> 4) ? 16u : 0u);
    const uint32_t b_loff = (uint32_t)((l & 7) * PPIT) + (((l >> 3) & 1) ? 16u : 0u)
                          + (((l >> 4) & 1) ? 8u * PPIT : 0u);
    const uint32_t aH = (uint32_t)__cvta_generic_to_shared(AH) + a_loff;
    const uint32_t aL = (uint32_t)__cvta_generic_to_shared(AL) + a_loff;
    const uint32_t bH = (uint32_t)__cvta_generic_to_shared(BH) + b_loff;
    const uint32_t bL = (uint32_t)__cvta_generic_to_shared(BL) + b_loff;

    const uint4* xh4 = (const uint4*)g_xh;
    const uint4* xl4 = (const uint4*)g_xl;

    const int ntiles = (NN + 127) / 128;

    auto stageA = [&](int base) {
        #pragma unroll
        for (int s = 0; s < 4; s++) {
            int i = s * 256 + tid;
            int r = i >> 3, q = i & 7;
            int gn = base + r; if (gn >= NN) gn = NN - 1;
            cpa16(AH + r * PPIT + q * 16, &xh4[gn * 8 + q]);
            cpa16(AL + r * PPIT + q * 16, &xl4[gn * 8 + q]);
        }
    };

    if (blockIdx.x < ntiles) stageA(blockIdx.x * 128);
    CPA_COMMIT();

    for (int tile = blockIdx.x; tile < ntiles; tile += gridDim.x) {
        const int base = tile * 128;
        CPA_WAIT0();
        __syncthreads();

        float C[16][4];
        #pragma unroll
        for (int nt = 0; nt < 16; nt++) {
            C[nt][0] = 0.f; C[nt][1] = 0.f; C[nt][2] = 0.f; C[nt][3] = 0.f;
        }

        #pragma unroll
        for (int ks = 0; ks < 4; ks++) {
            unsigned Ah[4], Al4[4];
            ldsm4(Ah[0], Ah[1], Ah[2], Ah[3], aH + ks * 32);
            ldsm4(Al4[0], Al4[1], Al4[2], Al4[3], aL + ks * 32);
            #pragma unroll
            for (int ntp = 0; ntp < 8; ntp++) {
                unsigned Bh[4], Bl[4];
                ldsm4(Bh[0], Bh[1], Bh[2], Bh[3], bH + ntp * 16 * PPIT + ks * 32);
                ldsm4(Bl[0], Bl[1], Bl[2], Bl[3], bL + ntp * 16 * PPIT + ks * 32);
                mma16816(C[2 * ntp],     Ah,  Bh);
                mma16816(C[2 * ntp],     Ah,  Bl);
                mma16816(C[2 * ntp],     Al4, Bh);
                mma16816(C[2 * ntp + 1], Ah,  Bh + 2);
                mma16816(C[2 * ntp + 1], Ah,  Bl + 2);
                mma16816(C[2 * ntp + 1], Al4, Bh + 2);
            }
        }
        __syncthreads();

        int nxt = tile + gridDim.x;
        if (nxt < ntiles) stageA(nxt * 128);
        CPA_COMMIT();

        int r0 = base + (w << 4) + (l >> 2);
        int r1 = r0 + 8;
        int cc = (l & 3) * 2;
        #pragma unroll
        for (int nt = 0; nt < 8; nt++) {
            int col = nt * 8 + cc;
            if (r0 < NN) *(float2*)(g_p1 + (size_t)r0 * H + col) = make_float2(C[nt][0], C[nt][1]);
            if (r1 < NN) *(float2*)(g_p1 + (size_t)r1 * H + col) = make_float2(C[nt][2], C[nt][3]);
        }
        #pragma unroll
        for (int nt = 8; nt < 16; nt++) {
            int col = (nt - 8) * 8 + cc;
            float2 bb = bias2[nt - 8];
            if (r0 < NN) *(float2*)(g_p2 + (size_t)r0 * H + col) =
                make_float2(C[nt][0] + bb.x, C[nt][1] + bb.y);
            if (r1 < NN) *(float2*)(g_p2 + (size_t)r1 * H + col) =
                make_float2(C[nt][2] + bb.x, C[nt][3] + bb.y);
        }
    }
}

// ---------- CSR edge pass (2-way unrolled): agg[n] -> bf16 hi/lo ----------
__global__ __launch_bounds__(NT) void k_edge() {
    int idx = blockIdx.x * NT + threadIdx.x;
    int n = idx >> 3, q = idx & 7;
    int s0 = g_off[n], s1 = g_off[n + 1];
    const float4* p2 = (const float4*)(g_p2 + (size_t)n * H) + q * 2;
    float4 b0 = p2[0], b1 = p2[1];
    float a[8] = {0.f, 0.f, 0.f, 0.f, 0.f, 0.f, 0.f, 0.f};
    int i = s0;
    for (; i + 2 <= s1; i += 2) {
        int src0 = g_csr[i], src1 = g_csr[i + 1];
        const float4* pa = (const float4*)(g_p1 + (size_t)src0 * H) + q * 2;
        const float4* pb = (const float4*)(g_p1 + (size_t)src1 * H) + q * 2;
        float4 c0 = pa[0], c1 = pa[1];
        float4 d0 = pb[0], d1 = pb[1];
        a[0] += fmaxf(c0.x + b0.x, 0.f) + fmaxf(d0.x + b0.x, 0.f);
        a[1] += fmaxf(c0.y + b0.y, 0.f) + fmaxf(d0.y + b0.y, 0.f);
        a[2] += fmaxf(c0.z + b0.z, 0.f) + fmaxf(d0.z + b0.z, 0.f);
        a[3] += fmaxf(c0.w + b0.w, 0.f) + fmaxf(d0.w + b0.w, 0.f);
        a[4] += fmaxf(c1.x + b1.x, 0.f) + fmaxf(d1.x + b1.x, 0.f);
        a[5] += fmaxf(c1.y + b1.y, 0.f) + fmaxf(d1.y + b1.y, 0.f);
        a[6] += fmaxf(c1.z + b1.z, 0.f) + fmaxf(d1.z + b1.z, 0.f);
        a[7] += fmaxf(c1.w + b1.w, 0.f) + fmaxf(d1.w + b1.w, 0.f);
    }
    if (i < s1) {
        int src = g_csr[i];
        const float4* p1 = (const float4*)(g_p1 + (size_t)src * H) + q * 2;
        float4 c0 = p1[0], c1 = p1[1];
        a[0] += fmaxf(c0.x + b0.x, 0.f); a[1] += fmaxf(c0.y + b0.y, 0.f);
        a[2] += fmaxf(c0.z + b0.z, 0.f); a[3] += fmaxf(c0.w + b0.w, 0.f);
        a[4] += fmaxf(c1.x + b1.x, 0.f); a[5] += fmaxf(c1.y + b1.y, 0.f);
        a[6] += fmaxf(c1.z + b1.z, 0.f); a[7] += fmaxf(c1.w + b1.w, 0.f);
    }
    float ic = 1.0f / fmaxf((float)(s1 - s0), 1.0f);
    __nv_bfloat162 h[4], lo[4];
    #pragma unroll
    for (int j = 0; j < 4; j++) split2(a[2 * j] * ic, a[2 * j + 1] * ic, h[j], lo[j]);
    *(uint4*)(g_ah + (size_t)n * 32 + q * 4) = *(uint4*)h;
    *(uint4*)(g_al + (size_t)n * 32 + q * 4) = *(uint4*)lo;
}

// ---------- tensor-core update + residual (from smem) + LayerNorm (+final reduce) ----------
template <bool FINAL>
__global__ __launch_bounds__(256, 2) void k_upd_t(int layer, const float* __restrict__ B,
                                                  const float* __restrict__ lng,
                                                  const float* __restrict__ lnb) {
    extern __shared__ char smc[];
    char* AH = smc;
    char* AL = AH + 128 * UPIT;
    char* BH = AL + 128 * UPIT;
    char* BL = BH + 64 * UPIT;
    float* prm = (float*)(BL + 64 * UPIT);           // bias[64], g[64], b2[64]
    float* fsum = prm + 192;
    unsigned* fmax = (unsigned*)(fsum + 64);

    const int tid = threadIdx.x;
    const int w = tid >> 5, l = tid & 31;

    {
        const uint4* sh = (const uint4*)(g_uh + layer * 64 * 136);
        const uint4* sl = (const uint4*)(g_ul + layer * 64 * 136);
        for (int i = tid; i < 1088; i += 256) {
            ((uint4*)BH)[i] = sh[i];
            ((uint4*)BL)[i] = sl[i];
        }
        if (tid < 64) {
            prm[tid] = B[tid];
            prm[64 + tid] = lng[tid];
            prm[128 + tid] = lnb[tid];
            if (FINAL) { fsum[tid] = 0.f; fmax[tid] = 0u; }
        }
    }

    const uint32_t a_loff = (uint32_t)(((w << 4) + (l & 15)) * UPIT) + ((l >> 4) ? 16u : 0u);
    const uint32_t b_loff = (uint32_t)((l & 7) * UPIT) + (((l >> 3) & 1) ? 16u : 0u)
                          + (((l >> 4) & 1) ? 8u * UPIT : 0u);
    const uint32_t aH = (uint32_t)__cvta_generic_to_shared(AH) + a_loff;
    const uint32_t aL = (uint32_t)__cvta_generic_to_shared(AL) + a_loff;
    const uint32_t bH = (uint32_t)__cvta_generic_to_shared(BH) + b_loff;
    const uint32_t bL = (uint32_t)__cvta_generic_to_shared(BL) + b_loff;

    const uint4* xh4 = (const uint4*)g_xh;
    const uint4* xl4 = (const uint4*)g_xl;
    const uint4* ah4 = (const uint4*)g_ah;
    const uint4* al4 = (const uint4*)g_al;

    const int ntiles = (NN + 127) / 128;

    auto stageA = [&](int base) {
        #pragma unroll
        for (int s = 0; s < 8; s++) {
            int i = s * 256 + tid;
            int r = i >> 4, q = i & 15;
            int gn = base + r; if (gn >= NN) gn = NN - 1;
            const uint4* srch = (q < 8) ? &xh4[gn * 8 + q] : &ah4[gn * 8 + (q - 8)];
            const uint4* srcl = (q < 8) ? &xl4[gn * 8 + q] : &al4[gn * 8 + (q - 8)];
            cpa16(AH + r * UPIT + q * 16, srch);
            cpa16(AL + r * UPIT + q * 16, srcl);
        }
    };

    float ls[16], lm[16];
    if (FINAL) {
        #pragma unroll
        for (int i = 0; i < 16; i++) { ls[i] = 0.f; lm[i] = -3.402823466e38f; }
    }

    if (blockIdx.x < ntiles) stageA(blockIdx.x * 128);
    CPA_COMMIT();

    // local rows this thread's epilogue owns
    const int lr0 = (w << 4) + (l >> 2);
    const int lr1 = lr0 + 8;
    const int cc = (l & 3) * 2;

    for (int tile = blockIdx.x; tile < ntiles; tile += gridDim.x) {
        const int base = tile * 128;
        CPA_WAIT0();
        __syncthreads();

        float C[8][4];
        #pragma unroll
        for (int nt = 0; nt < 8; nt++) {
            C[nt][0] = 0.f; C[nt][1] = 0.f; C[nt][2] = 0.f; C[nt][3] = 0.f;
        }

        #pragma unroll
        for (int ks = 0; ks < 8; ks++) {
            unsigned Ah[4], Al4r[4];
            ldsm4(Ah[0], Ah[1], Ah[2], Ah[3], aH + ks * 32);
            ldsm4(Al4r[0], Al4r[1], Al4r[2], Al4r[3], aL + ks * 32);
            #pragma unroll
            for (int ntp = 0; ntp < 4; ntp++) {
                unsigned Bh[4], Bl[4];
                ldsm4(Bh[0], Bh[1], Bh[2], Bh[3], bH + ntp * 16 * UPIT + ks * 32);
                ldsm4(Bl[0], Bl[1], Bl[2], Bl[3], bL + ntp * 16 * UPIT + ks * 32);
                mma16816(C[2 * ntp],     Ah,   Bh);
                mma16816(C[2 * ntp],     Ah,   Bl);
                mma16816(C[2 * ntp],     Al4r, Bh);
                mma16816(C[2 * ntp + 1], Ah,   Bh + 2);
                mma16816(C[2 * ntp + 1], Ah,   Bl + 2);
                mma16816(C[2 * ntp + 1], Al4r, Bh + 2);
            }
        }
        __syncthreads();

        // residual x = xh + xl from smem (this tile's A, x-half = first 128 bf16 cols)
        float rx0[16], rx1[16];
        #pragma unroll
        for (int nt = 0; nt < 8; nt++) {
            int boff = (nt * 8 + cc) * 2;   // byte offset of col pair in row
            __nv_bfloat162 h0 = *(__nv_bfloat162*)(AH + lr0 * UPIT + boff);
            __nv_bfloat162 l0 = *(__nv_bfloat162*)(AL + lr0 * UPIT + boff);
            __nv_bfloat162 h1 = *(__nv_bfloat162*)(AH + lr1 * UPIT + boff);
            __nv_bfloat162 l1 = *(__nv_bfloat162*)(AL + lr1 * UPIT + boff);
            rx0[2 * nt]     = __bfloat162float(h0.x) + __bfloat162float(l0.x);
            rx0[2 * nt + 1] = __bfloat162float(h0.y) + __bfloat162float(l0.y);
            rx1[2 * nt]     = __bfloat162float(h1.x) + __bfloat162float(l1.x);
            rx1[2 * nt + 1] = __bfloat162float(h1.y) + __bfloat162float(l1.y);
        }
        __syncthreads();   // residual reads done before anyone restages A

        int nxt = tile + gridDim.x;
        if (nxt < ntiles) stageA(nxt * 128);
        CPA_COMMIT();

        // LN epilogue (overlaps staging)
        int rr0 = base + lr0;
        int rr1 = base + lr1;
        float h0[8], h1[8];
        float s1a = 0.f, s2a = 0.f, s1b = 0.f, s2b = 0.f;
        #pragma unroll
        for (int nt = 0; nt < 8; nt++) {
            int col = nt * 8 + cc;
            float bx = prm[col], by = prm[col + 1];
            float v0 = fmaxf(C[nt][0] + bx, 0.f) + rx0[2 * nt];
            float v1 = fmaxf(C[nt][1] + by, 0.f) + rx0[2 * nt + 1];
            float v2 = fmaxf(C[nt][2] + bx, 0.f) + rx1[2 * nt];
            float v3 = fmaxf(C[nt][3] + by, 0.f) + rx1[2 * nt + 1];
            h0[nt] = v0; h1[nt] = v2;
            s1a += v0 + v1; s2a += v0 * v0 + v1 * v1;
            s1b += v2 + v3; s2b += v2 * v2 + v3 * v3;
            C[nt][1] = v1; C[nt][3] = v3;
        }
        #pragma unroll
        for (int d = 1; d < 4; d <<= 1) {
            s1a += __shfl_xor_sync(0xFFFFFFFFu, s1a, d);
            s2a += __shfl_xor_sync(0xFFFFFFFFu, s2a, d);
            s1b += __shfl_xor_sync(0xFFFFFFFFu, s1b, d);
            s2b += __shfl_xor_sync(0xFFFFFFFFu, s2b, d);
        }
        float mua = s1a * 0.015625f, mub = s1b * 0.015625f;
        float sca = rsqrtf(fmaxf(s2a * 0.015625f - mua * mua, 0.f) + 1e-5f);
        float scb = rsqrtf(fmaxf(s2b * 0.015625f - mub * mub, 0.f) + 1e-5f);
        #pragma unroll
        for (int nt = 0; nt < 8; nt++) {
            int col = nt * 8 + cc;
            float gx = prm[64 + col], gy = prm[65 + col];
            float bx = prm[128 + col], by = prm[129 + col];
            if (rr0 < NN) {
                float o0 = (h0[nt] - mua) * sca * gx + bx;
                float o1 = (C[nt][1] - mua) * sca * gy + by;
                if (FINAL) {
                    ls[2 * nt] += o0; ls[2 * nt + 1] += o1;
                    lm[2 * nt] = fmaxf(lm[2 * nt], o0);
                    lm[2 * nt + 1] = fmaxf(lm[2 * nt + 1], o1);
                } else {
                    __nv_bfloat162 hh, ll;
                    split2(o0, o1, hh, ll);
                    g_xh[(size_t)rr0 * 32 + (col >> 1)] = hh;
                    g_xl[(size_t)rr0 * 32 + (col >> 1)] = ll;
                }
            }
            if (rr1 < NN) {
                float o2 = (h1[nt] - mub) * scb * gx + bx;
                float o3 = (C[nt][3] - mub) * scb * gy + by;
                if (FINAL) {
                    ls[2 * nt] += o2; ls[2 * nt + 1] += o3;
                    lm[2 * nt] = fmaxf(lm[2 * nt], o2);
                    lm[2 * nt + 1] = fmaxf(lm[2 * nt + 1], o3);
                } else {
                    __nv_bfloat162 hh, ll;
                    split2(o2, o3, hh, ll);
                    g_xh[(size_t)rr1 * 32 + (col >> 1)] = hh;
                    g_xl[(size_t)rr1 * 32 + (col >> 1)] = ll;
                }
            }
        }
    }

    if (FINAL) {
        __syncthreads();
        #pragma unroll
        for (int nt = 0; nt < 8; nt++) {
            int col = nt * 8 + cc;
            atomicAdd(&fsum[col], ls[2 * nt]);
            atomicAdd(&fsum[col + 1], ls[2 * nt + 1]);
            atomicMax(&fmax[col], encf(lm[2 * nt]));
            atomicMax(&fmax[col + 1], encf(lm[2 * nt + 1]));
        }
        __syncthreads();
        if (tid < 64) {
            atomicAdd(&g_sum[tid], fsum[tid]);
            atomicMax(&g_maxb[tid], fmax[tid]);
        }
    }
}

__global__ void k_final(float* out) {
    int t = threadIdx.x;
    if (t < 64) out[t] = g_sum[t] * (1.0f / NN);
    else        out[t] = decf(g_maxb[t - 64]);
}

// ---------- launch ----------
extern "C" void kernel_launch(void* const* d_in, const int* in_sizes, int n_in,
                              void* d_out, int out_size) {
    const int*   ti    = (const int*)d_in[0];
    const int*   edges = (const int*)d_in[1];
    const float* et    = (const float*)d_in[2];
    const float* msg_w = (const float*)d_in[3];
    const float* msg_b = (const float*)d_in[4];
    const float* upd_w = (const float*)d_in[5];
    const float* upd_b = (const float*)d_in[6];
    const float* lng   = (const float*)d_in[7];
    const float* lnb   = (const float*)d_in[8];
    float* out = (float*)d_out;

    cudaFuncSetAttribute(k_proj_t, cudaFuncAttributeMaxDynamicSharedMemorySize, SMEM_PROJT);
    cudaFuncSetAttribute(k_upd_t<false>, cudaFuncAttributeMaxDynamicSharedMemorySize, SMEM_UPDT);
    cudaFuncSetAttribute(k_upd_t<true>,  cudaFuncAttributeMaxDynamicSharedMemorySize, SMEM_UPDT);

    k_setup<<<512, 256>>>(ti, et, msg_w, upd_w);
    k_hist<<<512, 256>>>(edges);
    k_scan1<<<NBLK, 256>>>();
    // layer-0 proj placed 4th so ncu (-s5 -c1) profiles it
    k_proj_t<<<296, 256, SMEM_PROJT>>>(0, msg_b);
    k_scan2<<<1, 512>>>();
    k_scan3<<<392, 256>>>();
    k_scatter<<<(NE + 255) / 256, 256>>>(edges);

    for (int l = 0; l < 3; l++) {
        if (l > 0) k_proj_t<<<296, 256, SMEM_PROJT>>>(l, msg_b + l * 64);
        k_edge<<<NN * 8 / NT, NT>>>();
        if (l < 2)
            k_upd_t<false><<<296, 256, SMEM_UPDT>>>(l, upd_b + l * 64, lng + l * 64, lnb + l * 64);
        else
            k_upd_t<true><<<296, 256, SMEM_UPDT>>>(l, upd_b + l * 64, lng + l * 64, lnb + l * 64);
    }

    k_final<<<1, 128>>>(out);
}